// round 13
// baseline (speedup 1.0000x reference)
#include <cuda_runtime.h>
#include <cuda_bf16.h>
#include <cuda_fp8.h>
#include <cstdint>
#include <math.h>

#define Nn 8192
#define NJOBS 2080                     // 64*65/2 upper-triangle 128x128 tile pairs
#define NCTA 304                       // 2 CTAs per SM
#define TS 16384                       // fp8 tile bytes: 128 rows x 128B
#define NEG_C 2.3195228352514835e-16f  /* exp(-36) */

__device__ unsigned char g_xq[Nn * 128]; // normalized e4m3 rows (128B/row)
__device__ int   g_tgt[Nn];
__device__ float g_acc[3 * Nn];          // [0,Nn): sp(excl diag)  [Nn,2Nn): sn  [2Nn,3Nn): cn

// ---------------- helpers ----------------
__device__ __forceinline__ uint32_t s2u(const void* p) {
    uint32_t a;
    asm("{ .reg .u64 t; cvta.to.shared.u64 t, %1; cvt.u32.u64 %0, t; }" : "=r"(a) : "l"(p));
    return a;
}
__device__ __forceinline__ void cp16(uint32_t s, const void* g) {
    asm volatile("cp.async.cg.shared.global [%0], [%1], 16;"
                 :: "r"(s), "l"(__cvta_generic_to_global(g)) : "memory");
}
__device__ __forceinline__ void cp_commit() {
    asm volatile("cp.async.commit_group;" ::: "memory");
}
__device__ __forceinline__ void cp_wait0() {
    asm volatile("cp.async.wait_group 0;" ::: "memory");
}
__device__ __forceinline__ void cp_wait1() {
    asm volatile("cp.async.wait_group 1;" ::: "memory");
}
__device__ __forceinline__ void ldsm4(uint32_t (&r)[4], uint32_t addr) {
    asm volatile("ldmatrix.sync.aligned.m8n8.x4.shared.b16 {%0,%1,%2,%3}, [%4];"
                 : "=r"(r[0]), "=r"(r[1]), "=r"(r[2]), "=r"(r[3]) : "r"(addr));
}
__device__ __forceinline__ void mma_fp8(float (&c)[4], const uint32_t* a,
                                        uint32_t b0, uint32_t b1) {
    asm volatile(
        "mma.sync.aligned.m16n8k32.row.col.f32.e4m3.e4m3.f32 "
        "{%0,%1,%2,%3}, {%4,%5,%6,%7}, {%8,%9}, {%0,%1,%2,%3};"
        : "+f"(c[0]), "+f"(c[1]), "+f"(c[2]), "+f"(c[3])
        : "r"(a[0]), "r"(a[1]), "r"(a[2]), "r"(a[3]), "r"(b0), "r"(b1));
}
// swizzled byte offset within a 128x128-fp8 tile (128B rows, XOR on 16B chunks)
__device__ __forceinline__ uint32_t soff8(int row, int ch) {
    return (uint32_t)((row << 7) + ((ch ^ (row & 7)) << 4));
}
// triangular decode: job L -> (bi <= bj), offset(b) = 64b - b(b-1)/2
__device__ __forceinline__ void decode(int L, int& bi, int& bj) {
    int b = (int)((129.0f - sqrtf(16641.0f - 8.0f * (float)L)) * 0.5f);
    while (64 * (b + 1) - ((b + 1) * b) / 2 <= L) b++;
    while (64 * b - (b * (b - 1)) / 2 > L) b--;
    bi = b;
    bj = b + (L - (64 * b - (b * (b - 1)) / 2));
}

// ---------------- prep: normalize + e4m3 convert + targets + zero acc/out ----------------
__global__ void k_prep(const float* __restrict__ x, const int* __restrict__ t,
                       float* __restrict__ out) {
    if (blockIdx.x == 0 && threadIdx.x == 0) out[0] = 0.f;
    int gidx = blockIdx.x * 256 + threadIdx.x;
    if (gidx < 3 * Nn) g_acc[gidx] = 0.f;
    int row  = blockIdx.x * 8 + (threadIdx.x >> 5);
    int lane = threadIdx.x & 31;
    if (threadIdx.x < 8) g_tgt[blockIdx.x * 8 + threadIdx.x] = t[blockIdx.x * 8 + threadIdx.x];
    float4 v = reinterpret_cast<const float4*>(x + (size_t)row * 128)[lane];
    float s = v.x * v.x + v.y * v.y + v.z * v.z + v.w * v.w;
#pragma unroll
    for (int o = 16; o; o >>= 1) s += __shfl_xor_sync(0xffffffffu, s, o);
    float inv = rsqrtf(s);
    __nv_fp8x2_storage_t lo = __nv_cvt_float2_to_fp8x2(
        make_float2(v.x * inv, v.y * inv), __NV_SATFINITE, __NV_E4M3);
    __nv_fp8x2_storage_t hi = __nv_cvt_float2_to_fp8x2(
        make_float2(v.z * inv, v.w * inv), __NV_SATFINITE, __NV_E4M3);
    uint32_t packed = (uint32_t)lo | ((uint32_t)hi << 16);
    reinterpret_cast<uint32_t*>(g_xq)[row * 32 + lane] = packed;
}

// ---------------- main: persistent triangle fp8 HMMA, 2 CTAs/SM ----------------
// grid = 304, 256 threads (8 warps, 4x2 over 128x128 tile, 32x64/warp).
// SMEM per CTA: A double [0,32K) + B double [32K,64K). Two CTAs per SM give
// independent barrier domains -> latency of one CTA hidden by the other.
extern __shared__ char smem[];

__global__ void __launch_bounds__(256, 2) k_main() {
    int tid = threadIdx.x, wid = tid >> 5, lane = tid & 31;
    uint32_t sb = s2u(smem);
    const char* gX = (const char*)g_xq;

    int m0 = (wid & 3) * 32, n0 = (wid >> 2) * 64;

    int nstart = (int)(((long long)blockIdx.x * NJOBS) / NCTA);
    int nend   = (int)(((long long)(blockIdx.x + 1) * NJOBS) / NCTA);

    int bi, bj;
    decode(nstart, bi, bj);

    // prologue: A(bi) -> abuf0, B(bj) -> bbuf0
#pragma unroll
    for (int q = 0; q < 4; q++) {
        int g = tid + 256 * q, row = g >> 3, ch = g & 7;
        uint32_t o = soff8(row, ch);
        cp16(sb + o,         gX + (size_t)(bi * 128 + row) * 128 + ch * 16);
        cp16(sb + 32768 + o, gX + (size_t)(bj * 128 + row) * 128 + ch * 16);
    }
    cp_commit();

    int pa = 0, pb = 0;
    for (int L = nstart; L < nend; L++) {
        bool hn = (L + 1 < nend);
        bool aswap = false;
        if (hn) {
            int bin = bi, bjn = bj + 1;
            if (bjn == 64) { bin = bi + 1; bjn = bin; }
            if (bin != bi) {
                aswap = true;
#pragma unroll
                for (int q = 0; q < 4; q++) {
                    int g = tid + 256 * q, row = g >> 3, ch = g & 7;
                    cp16(sb + (pa ^ 1) * TS + soff8(row, ch),
                         gX + (size_t)(bin * 128 + row) * 128 + ch * 16);
                }
            }
#pragma unroll
            for (int q = 0; q < 4; q++) {
                int g = tid + 256 * q, row = g >> 3, ch = g & 7;
                cp16(sb + 32768 + (pb ^ 1) * TS + soff8(row, ch),
                     gX + (size_t)(bjn * 128 + row) * 128 + ch * 16);
            }
            cp_commit();
        }

        if (hn) cp_wait1(); else cp_wait0();
        __syncthreads();

        int i0 = bi * 128, j0 = bj * 128;
        bool diag = (bi == bj);

        // ---- GEMM: this warp's 32x64 slice (4 x k32 steps) ----
        float acc[2][8][4];
#pragma unroll
        for (int mf = 0; mf < 2; mf++)
#pragma unroll
            for (int nf = 0; nf < 8; nf++)
#pragma unroll
                for (int e2 = 0; e2 < 4; e2++) acc[mf][nf][e2] = 0.f;

        uint32_t Ab = sb + pa * TS, Bb = sb + 32768 + pb * TS;
        {
            int arow = m0 + ((lane >> 3) & 1) * 8 + (lane & 7);
            int ach  = (lane >> 4);
            int brow = n0 + (lane >> 4) * 8 + (lane & 7);
            int bch  = ((lane >> 3) & 1);
#pragma unroll
            for (int ks = 0; ks < 4; ks++) {
                uint32_t aF[2][4], bF[4][4];
                ldsm4(aF[0], Ab + soff8(arow,      ks * 2 + ach));
                ldsm4(aF[1], Ab + soff8(arow + 16, ks * 2 + ach));
#pragma unroll
                for (int nf2 = 0; nf2 < 4; nf2++)
                    ldsm4(bF[nf2], Bb + soff8(brow + nf2 * 16, ks * 2 + bch));
#pragma unroll
                for (int mf = 0; mf < 2; mf++)
#pragma unroll
                    for (int nf2 = 0; nf2 < 4; nf2++) {
                        mma_fp8(acc[mf][nf2 * 2 + 0], aF[mf], bF[nf2][0], bF[nf2][1]);
                        mma_fp8(acc[mf][nf2 * 2 + 1], aF[mf], bF[nf2][2], bF[nf2][3]);
                    }
            }
        }

        __syncthreads();  // all ldsm reads of both buffers done -> next prefetch safe

        // ---- epilogue: rare path straight to global (fire-and-forget atomics) ----
#pragma unroll
        for (int nf2 = 0; nf2 < 4; nf2++)
#pragma unroll
            for (int par = 0; par < 2; par++) {
                int colb = n0 + nf2 * 16 + par * 8 + (lane & 3) * 2;
                int nf = nf2 * 2 + par;
#pragma unroll
                for (int mf = 0; mf < 2; mf++)
#pragma unroll
                    for (int h = 0; h < 2; h++) {
                        int rl = m0 + mf * 16 + h * 8 + (lane >> 2);
#pragma unroll
                        for (int e2 = 0; e2 < 2; e2++) {
                            float s = acc[mf][nf][h * 2 + e2];
                            if (s > 0.25f) {               // rare (~0.25%)
                                int gi = i0 + rl, gj = j0 + colb + e2;
                                if (gi != gj) {            // diagonal added exactly in k_final
                                    int tiv = g_tgt[gi], tjv = g_tgt[gj];
                                    if (tiv == tjv) {
                                        float ev = __expf(fmaf(64.f * (1.25f - s),
                                                               s - 0.75f, -4.f));
                                        atomicAdd(&g_acc[gi], ev);
                                        if (!diag) atomicAdd(&g_acc[gj], ev);
                                    } else {
                                        float tt = s - 0.25f;
                                        float ev = __expf(fmaf(64.f * tt, tt, -36.f));
                                        atomicAdd(&g_acc[Nn + gi], ev);
                                        atomicAdd(&g_acc[2 * Nn + gi], 1.f);
                                        if (!diag) {
                                            atomicAdd(&g_acc[Nn + gj], ev);
                                            atomicAdd(&g_acc[2 * Nn + gj], 1.f);
                                        }
                                    }
                                }
                            }
                        }
                    }
            }

        pb ^= 1;
        if (aswap) pa ^= 1;
        bj++;
        if (bj == 64) { bi++; bj = bi; }
    }
}

// ---------------- final: histogram + log + softplus + partial mean (grid 32) ------------
__global__ void k_final(float* __restrict__ out) {
    __shared__ int hist[512];
    __shared__ float red[8];
    int tid = threadIdx.x;  // 256
    hist[tid] = 0; hist[tid + 256] = 0;
    __syncthreads();
    for (int i = tid; i < Nn; i += 256) atomicAdd(&hist[g_tgt[i]], 1);
    __syncthreads();

    float acc = 0.f;
    int base = blockIdx.x * (Nn / 32);
    for (int q = 0; q < Nn / 32 / 256; q++) {
        int i = base + q * 256 + tid;
        float spv = g_acc[i] + 1.0f;                          // +1 = exact diagonal term
        float below = (float)(Nn - hist[g_tgt[i]]) - g_acc[2 * Nn + i];
        float snv = g_acc[Nn + i] + below * NEG_C;            // >= ~1.9e-12
        float z = 40.f + logf(spv) + logf(snv);               // >= ~13 > 0
        acc += z + log1pf(__expf(-z));                        // softplus, stable for z>0
    }
#pragma unroll
    for (int o = 16; o; o >>= 1) acc += __shfl_xor_sync(0xffffffffu, acc, o);
    if ((tid & 31) == 0) red[tid >> 5] = acc;
    __syncthreads();
    if (tid == 0) {
        float s = 0.f;
#pragma unroll
        for (int w = 0; w < 8; w++) s += red[w];
        atomicAdd(out, s / (float)Nn);
    }
}

extern "C" void kernel_launch(void* const* d_in, const int* in_sizes, int n_in,
                              void* d_out, int out_size) {
    const float* x  = (const float*)d_in[0];
    const int*   tg = (const int*)d_in[1];
    float* out = (float*)d_out;

    cudaFuncSetAttribute(k_main, cudaFuncAttributeMaxDynamicSharedMemorySize, 65536);

    k_prep<<<Nn / 8, 256>>>(x, tg, out);
    k_main<<<NCTA, 256, 65536>>>();
    k_final<<<32, 256>>>(out);
}

// round 14
// speedup vs baseline: 1.4273x; 1.4273x over previous
#include <cuda_runtime.h>
#include <cuda_fp8.h>
#include <cstdint>
#include <math.h>

#define Nn 8192
#define NJOBS 2080                     // 64*65/2 upper-triangle 128x128 tile pairs
#define NCTA 148                       // one wave, guaranteed co-resident
#define TS 16384                       // fp8 tile bytes: 128 rows x 128B
#define NEG_C 2.3195228352514835e-16f  /* exp(-36) */

__device__ unsigned char g_xq[Nn * 128]; // normalized e4m3 rows (128B/row)
__device__ int   g_tgt[Nn];
__device__ float g_acc[3 * Nn];          // sp(excl diag) | sn | cn
__device__ float g_part[32];
__device__ int   g_b1, g_b2, g_b3;       // spin barriers (reset at kernel end)

// ---------------- helpers ----------------
__device__ __forceinline__ uint32_t s2u(const void* p) {
    uint32_t a;
    asm("{ .reg .u64 t; cvta.to.shared.u64 t, %1; cvt.u32.u64 %0, t; }" : "=r"(a) : "l"(p));
    return a;
}
__device__ __forceinline__ void cp16(uint32_t s, const void* g) {
    asm volatile("cp.async.cg.shared.global [%0], [%1], 16;"
                 :: "r"(s), "l"(__cvta_generic_to_global(g)) : "memory");
}
__device__ __forceinline__ void cp_commit() {
    asm volatile("cp.async.commit_group;" ::: "memory");
}
__device__ __forceinline__ void cp_wait0() {
    asm volatile("cp.async.wait_group 0;" ::: "memory");
}
__device__ __forceinline__ void cp_wait1() {
    asm volatile("cp.async.wait_group 1;" ::: "memory");
}
__device__ __forceinline__ void ldsm4(uint32_t (&r)[4], uint32_t addr) {
    asm volatile("ldmatrix.sync.aligned.m8n8.x4.shared.b16 {%0,%1,%2,%3}, [%4];"
                 : "=r"(r[0]), "=r"(r[1]), "=r"(r[2]), "=r"(r[3]) : "r"(addr));
}
__device__ __forceinline__ void mma_fp8(float (&c)[4], const uint32_t* a,
                                        uint32_t b0, uint32_t b1) {
    asm volatile(
        "mma.sync.aligned.m16n8k32.row.col.f32.e4m3.e4m3.f32 "
        "{%0,%1,%2,%3}, {%4,%5,%6,%7}, {%8,%9}, {%0,%1,%2,%3};"
        : "+f"(c[0]), "+f"(c[1]), "+f"(c[2]), "+f"(c[3])
        : "r"(a[0]), "r"(a[1]), "r"(a[2]), "r"(a[3]), "r"(b0), "r"(b1));
}
__device__ __forceinline__ uint32_t soff8(int row, int ch) {
    return (uint32_t)((row << 7) + ((ch ^ (row & 7)) << 4));
}
__device__ __forceinline__ void decode(int L, int& bi, int& bj) {
    int b = (int)((129.0f - sqrtf(16641.0f - 8.0f * (float)L)) * 0.5f);
    while (64 * (b + 1) - ((b + 1) * b) / 2 <= L) b++;
    while (64 * b - (b * (b - 1)) / 2 > L) b--;
    bi = b;
    bj = b + (L - (64 * b - (b * (b - 1)) / 2));
}
// grid-wide barrier: all threads' prior work done -> arrive -> bounded spin
__device__ __forceinline__ void gbar(int* ctr, int tid) {
    __threadfence();
    __syncthreads();
    if (tid == 0) {
        atomicAdd(ctr, 1);
        long long n = 0;
        while (*(volatile int*)ctr < NCTA && n < (1LL << 26)) { __nanosleep(40); n++; }
    }
    __syncthreads();
    __threadfence();
}

// ---------------- fused: prep + triangle fp8 GEMM + reduction -------------------
// grid = 148, 512 threads (16 warps, 4x4 over 128x128 tile, 32x32/warp).
// SMEM: A double [0,32K) + B double [32K,64K); reused as hist in phase 3.
extern __shared__ char smem[];

__global__ void __launch_bounds__(512) k_all(const float* __restrict__ x,
                                             const int* __restrict__ t,
                                             float* __restrict__ out) {
    int tid = threadIdx.x, wid = tid >> 5, lane = tid & 31;
    int bid = blockIdx.x;
    uint32_t sb = s2u(smem);

    // ===== phase 1: zero accumulators, copy targets, normalize + e4m3 =====
    for (int idx = bid * 512 + tid; idx < 3 * Nn; idx += NCTA * 512) g_acc[idx] = 0.f;
    for (int idx = bid * 512 + tid; idx < Nn; idx += NCTA * 512) g_tgt[idx] = t[idx];
    for (int row = bid * 16 + wid; row < Nn; row += NCTA * 16) {
        float4 v = reinterpret_cast<const float4*>(x + (size_t)row * 128)[lane];
        float s = v.x * v.x + v.y * v.y + v.z * v.z + v.w * v.w;
#pragma unroll
        for (int o = 16; o; o >>= 1) s += __shfl_xor_sync(0xffffffffu, s, o);
        float inv = rsqrtf(s);
        __nv_fp8x2_storage_t lo = __nv_cvt_float2_to_fp8x2(
            make_float2(v.x * inv, v.y * inv), __NV_SATFINITE, __NV_E4M3);
        __nv_fp8x2_storage_t hi = __nv_cvt_float2_to_fp8x2(
            make_float2(v.z * inv, v.w * inv), __NV_SATFINITE, __NV_E4M3);
        reinterpret_cast<uint32_t*>(g_xq)[row * 32 + lane] =
            (uint32_t)lo | ((uint32_t)hi << 16);
    }
    gbar(&g_b1, tid);

    // ===== phase 2: persistent triangle fp8 GEMM (round-12 design) =====
    const char* gX = (const char*)g_xq;
    int m0 = (wid & 3) * 32, n0 = (wid >> 2) * 32;

    int nstart = (int)(((long long)bid * NJOBS) / NCTA);
    int nend   = (int)(((long long)(bid + 1) * NJOBS) / NCTA);

    int bi, bj;
    decode(nstart, bi, bj);

#pragma unroll
    for (int q = 0; q < 2; q++) {
        int g = tid + 512 * q, row = g >> 3, ch = g & 7;
        uint32_t o = soff8(row, ch);
        cp16(sb + o,         gX + (size_t)(bi * 128 + row) * 128 + ch * 16);
        cp16(sb + 32768 + o, gX + (size_t)(bj * 128 + row) * 128 + ch * 16);
    }
    cp_commit();

    int pa = 0, pb = 0;
    for (int L = nstart; L < nend; L++) {
        bool hn = (L + 1 < nend);
        bool aswap = false;
        if (hn) {
            int bin = bi, bjn = bj + 1;
            if (bjn == 64) { bin = bi + 1; bjn = bin; }
            if (bin != bi) {
                aswap = true;
#pragma unroll
                for (int q = 0; q < 2; q++) {
                    int g = tid + 512 * q, row = g >> 3, ch = g & 7;
                    cp16(sb + (pa ^ 1) * TS + soff8(row, ch),
                         gX + (size_t)(bin * 128 + row) * 128 + ch * 16);
                }
            }
#pragma unroll
            for (int q = 0; q < 2; q++) {
                int g = tid + 512 * q, row = g >> 3, ch = g & 7;
                cp16(sb + 32768 + (pb ^ 1) * TS + soff8(row, ch),
                     gX + (size_t)(bjn * 128 + row) * 128 + ch * 16);
            }
            cp_commit();
        }

        if (hn) cp_wait1(); else cp_wait0();
        __syncthreads();

        int i0 = bi * 128, j0 = bj * 128;
        bool diag = (bi == bj);

        float acc[2][4][4];
#pragma unroll
        for (int mf = 0; mf < 2; mf++)
#pragma unroll
            for (int nf = 0; nf < 4; nf++)
#pragma unroll
                for (int e2 = 0; e2 < 4; e2++) acc[mf][nf][e2] = 0.f;

        uint32_t Ab = sb + pa * TS, Bb = sb + 32768 + pb * TS;
        uint32_t aF[2][2][4], bF[2][2][4];
        {
            int arow = m0 + ((lane >> 3) & 1) * 8 + (lane & 7);
            int ach  = (lane >> 4);
            int brow = n0 + (lane >> 4) * 8 + (lane & 7);
            int bch  = ((lane >> 3) & 1);
            ldsm4(aF[0][0], Ab + soff8(arow,      ach));
            ldsm4(aF[0][1], Ab + soff8(arow + 16, ach));
            ldsm4(bF[0][0], Bb + soff8(brow,      bch));
            ldsm4(bF[0][1], Bb + soff8(brow + 16, bch));
#pragma unroll
            for (int ks = 0; ks < 4; ks++) {
                int c = ks & 1;
                if (ks < 3) {
                    int cn2 = c ^ 1, kn = ks + 1;
                    ldsm4(aF[cn2][0], Ab + soff8(arow,      kn * 2 + ach));
                    ldsm4(aF[cn2][1], Ab + soff8(arow + 16, kn * 2 + ach));
                    ldsm4(bF[cn2][0], Bb + soff8(brow,      kn * 2 + bch));
                    ldsm4(bF[cn2][1], Bb + soff8(brow + 16, kn * 2 + bch));
                }
#pragma unroll
                for (int mf = 0; mf < 2; mf++)
#pragma unroll
                    for (int nf2 = 0; nf2 < 2; nf2++) {
                        mma_fp8(acc[mf][nf2 * 2 + 0], aF[c][mf], bF[c][nf2][0], bF[c][nf2][1]);
                        mma_fp8(acc[mf][nf2 * 2 + 1], aF[c][mf], bF[c][nf2][2], bF[c][nf2][3]);
                    }
            }
        }

        __syncthreads();  // ldsm reads of both buffers done -> next prefetch safe

        // rare-path epilogue straight to global
#pragma unroll
        for (int nf2 = 0; nf2 < 2; nf2++)
#pragma unroll
            for (int par = 0; par < 2; par++) {
                int colb = n0 + nf2 * 16 + par * 8 + (lane & 3) * 2;
                int nf = nf2 * 2 + par;
#pragma unroll
                for (int mf = 0; mf < 2; mf++)
#pragma unroll
                    for (int h = 0; h < 2; h++) {
                        int rl = m0 + mf * 16 + h * 8 + (lane >> 2);
#pragma unroll
                        for (int e2 = 0; e2 < 2; e2++) {
                            float s = acc[mf][nf][h * 2 + e2];
                            if (s > 0.25f) {               // rare (~0.25%)
                                int gi = i0 + rl, gj = j0 + colb + e2;
                                if (gi != gj) {            // diagonal added exactly below
                                    int tiv = g_tgt[gi], tjv = g_tgt[gj];
                                    if (tiv == tjv) {
                                        float ev = __expf(fmaf(64.f * (1.25f - s),
                                                               s - 0.75f, -4.f));
                                        atomicAdd(&g_acc[gi], ev);
                                        if (!diag) atomicAdd(&g_acc[gj], ev);
                                    } else {
                                        float tt = s - 0.25f;
                                        float ev = __expf(fmaf(64.f * tt, tt, -36.f));
                                        atomicAdd(&g_acc[Nn + gi], ev);
                                        atomicAdd(&g_acc[2 * Nn + gi], 1.f);
                                        if (!diag) {
                                            atomicAdd(&g_acc[Nn + gj], ev);
                                            atomicAdd(&g_acc[2 * Nn + gj], 1.f);
                                        }
                                    }
                                }
                            }
                        }
                    }
            }

        pb ^= 1;
        if (aswap) pa ^= 1;
        bj++;
        if (bj == 64) { bi++; bj = bi; }
    }
    gbar(&g_b2, tid);

    // ===== phase 3: reduction on CTAs 0..31 (smem reused) =====
    if (bid < 32) {
        int*   hist = reinterpret_cast<int*>(smem);
        float* red  = reinterpret_cast<float*>(smem + 2048);
        hist[tid] = 0;
        __syncthreads();
        for (int i = tid; i < Nn; i += 512) atomicAdd(&hist[g_tgt[i]], 1);
        __syncthreads();

        float acc = 0.f;
        if (tid < 256) {
            int i = bid * 256 + tid;
            float spv = g_acc[i] + 1.0f;                          // exact diagonal term
            float below = (float)(Nn - hist[g_tgt[i]]) - g_acc[2 * Nn + i];
            float snv = g_acc[Nn + i] + below * NEG_C;
            float z = 40.f + logf(spv) + logf(snv);               // > 13
            acc = z + log1pf(__expf(-z));                         // softplus
        }
#pragma unroll
        for (int o = 16; o; o >>= 1) acc += __shfl_xor_sync(0xffffffffu, acc, o);
        if ((tid & 31) == 0) red[tid >> 5] = acc;
        __syncthreads();
        if (tid == 0) {
            float s = 0.f;
#pragma unroll
            for (int w = 0; w < 16; w++) s += red[w];
            g_part[bid] = s;
        }
    }
    // final arrive + CTA0 writes scalar and resets barriers for the next replay
    __threadfence();
    __syncthreads();
    if (tid == 0) {
        atomicAdd(&g_b3, 1);
        if (bid == 0) {
            long long n = 0;
            while (*(volatile int*)&g_b3 < NCTA && n < (1LL << 26)) { __nanosleep(40); n++; }
            __threadfence();
            float s = 0.f;
#pragma unroll
            for (int w = 0; w < 32; w++) s += g_part[w];
            out[0] = s / (float)Nn;
            g_b1 = 0; g_b2 = 0; g_b3 = 0;   // clean state for next graph replay
            __threadfence();
        }
    }
}

extern "C" void kernel_launch(void* const* d_in, const int* in_sizes, int n_in,
                              void* d_out, int out_size) {
    const float* x  = (const float*)d_in[0];
    const int*   tg = (const int*)d_in[1];
    float* out = (float*)d_out;

    cudaFuncSetAttribute(k_all, cudaFuncAttributeMaxDynamicSharedMemorySize, 65536);
    k_all<<<NCTA, 512, 65536>>>(x, tg, out);
}